// round 9
// baseline (speedup 1.0000x reference)
#include <cuda_runtime.h>

// MultiScaleRoIAlign: 4-level FPN, RoIAlign(aligned=False), OUT=7, SR=2.
// feats: [2,256,200,200],[2,256,100,100],[2,256,50,50],[2,256,25,25] fp32
// boxes: [2,256,4] fp32 -> out: [512,256,7,7] fp32
//
// v9: row-wise gather. One block (256 thr) per RoI, warp = channel stream.
// lane -> x-tap column (28 live): per y-tap (14), two LDGs read the SAME
// feature row at the 28 tap columns (1-4 cache lines each). Row-interp and
// per-lane x-weights, then shfl_xor(1) + shfl_xor(2) aggregate the 4 x-taps
// of each bin column; lane 4*pw keeps 7 bin-row accumulators. Y-tap geometry
// in a small smem table; x-tap geometry in 2 registers per lane.

#define NLVL 4

__global__ __launch_bounds__(256) void roi_align_kernel(
    const float* __restrict__ f0, const float* __restrict__ f1,
    const float* __restrict__ f2, const float* __restrict__ f3,
    const float* __restrict__ boxes, float* __restrict__ out)
{
    const int r    = blockIdx.x;     // roi 0..511
    const int tid  = threadIdx.x;
    const int w    = tid >> 5;       // warp 0..7
    const int lane = tid & 31;
    const int b    = r >> 8;

    // ---- per-RoI geometry ----
    const float bx1 = boxes[r * 4 + 0];
    const float by1 = boxes[r * 4 + 1];
    const float bx2 = boxes[r * 4 + 2];
    const float by2 = boxes[r * 4 + 3];

    const float area = (bx2 - bx1) * (by2 - by1);
    float lv = floorf(4.0f + log2f(sqrtf(area) / 224.0f + 1e-6f));
    lv = fminf(fmaxf(lv, 2.0f), 5.0f);
    const int level = (int)lv - 2;

    const int   Htab[NLVL]  = {200, 100, 50, 25};
    const float sctab[NLVL] = {0.25f, 0.125f, 0.0625f, 0.03125f};
    const int   H  = Htab[level];
    const int   W  = H;
    const float sc = sctab[level];
    const float* feat = (level == 0) ? f0 : (level == 1) ? f1 : (level == 2) ? f2 : f3;

    const float x1 = bx1 * sc, y1 = by1 * sc;
    const float roi_w = fmaxf(bx2 * sc - x1, 1.0f);
    const float roi_h = fmaxf(by2 * sc - y1, 1.0f);
    const float bin_w = roi_w / 7.0f;
    const float bin_h = roi_h / 7.0f;

    // ---- y-tap table (14 taps) in smem: row offsets + folded weights ----
    __shared__ int2   s_rows[14];   // (yl*W, yh*W)
    __shared__ float2 s_wy[14];     // (vy/4*(1-ly), vy/4*ly)

    if (tid < 14) {
        const int ph = tid >> 1;
        const int ii = tid & 1;
        const float g = (float)ph + ((float)ii + 0.5f) * 0.5f;
        float pos = y1 + g * bin_h;
        const float vld = (pos >= -1.0f && pos <= (float)H) ? 0.25f : 0.0f;  // fold /4
        pos = fmaxf(pos, 0.0f);
        int lo = (int)pos, hi;
        if (lo >= H - 1) { lo = H - 1; hi = H - 1; pos = (float)lo; }
        else             { hi = lo + 1; }
        const float fr = pos - (float)lo;
        s_rows[tid] = make_int2(lo * W, hi * W);
        s_wy[tid]   = make_float2(vld * (1.0f - fr), vld * fr);
    }

    // ---- per-lane x geometry: lane -> (x-tap = lane>>1, side = lane&1) ----
    int   col = 0;
    float wx  = 0.0f;
    if (lane < 28) {
        const int tap = lane >> 1;       // x-tap 0..13
        const int s   = lane & 1;        // 0 = xl, 1 = xh
        const int pw  = tap >> 1;
        const int ii  = tap & 1;
        const float g = (float)pw + ((float)ii + 0.5f) * 0.5f;
        float pos = x1 + g * bin_w;
        const float vld = (pos >= -1.0f && pos <= (float)W) ? 1.0f : 0.0f;
        pos = fmaxf(pos, 0.0f);
        int lo = (int)pos, hi;
        if (lo >= W - 1) { lo = W - 1; hi = W - 1; pos = (float)lo; }
        else             { hi = lo + 1; }
        const float fr = pos - (float)lo;
        col = s ? hi : lo;
        wx  = vld * (s ? fr : (1.0f - fr));
    }

    __syncthreads();

    // ---- sweep 32 channels per warp ----
    const size_t plane = (size_t)H * W;
    const float* fp = feat + ((size_t)b * 256 + (size_t)w * 32) * plane;
    float* op = out + ((size_t)r * 256 + (size_t)w * 32) * 49;

    const bool storer = ((lane & 3) == 0) && (lane < 28);
    const int  my_pw  = lane >> 2;

    #pragma unroll 1
    for (int k = 0; k < 32; k++) {
        float acc[7];
        #pragma unroll
        for (int i = 0; i < 7; i++) acc[i] = 0.0f;

        #pragma unroll
        for (int jy = 0; jy < 14; jy++) {
            const int2   rw = s_rows[jy];
            const float2 wy = s_wy[jy];
            const float lo = fp[rw.x + col];
            const float hi = fp[rw.y + col];
            float t = wx * (wy.x * lo + wy.y * hi);
            t += __shfl_xor_sync(0xFFFFFFFFu, t, 1);
            t += __shfl_xor_sync(0xFFFFFFFFu, t, 2);
            acc[jy >> 1] += t;
        }

        if (storer) {
            #pragma unroll
            for (int ph = 0; ph < 7; ph++)
                op[ph * 7 + my_pw] = acc[ph];
        }

        fp += plane;
        op += 49;
    }
}

extern "C" void kernel_launch(void* const* d_in, const int* in_sizes, int n_in,
                              void* d_out, int out_size) {
    const int nroi = in_sizes[4] / 4;   // 512
    roi_align_kernel<<<nroi, 256>>>(
        (const float*)d_in[0], (const float*)d_in[1],
        (const float*)d_in[2], (const float*)d_in[3],
        (const float*)d_in[4], (float*)d_out);
}

// round 10
// speedup vs baseline: 2.0659x; 2.0659x over previous
#include <cuda_runtime.h>

// MultiScaleRoIAlign: 4-level FPN, RoIAlign(aligned=False), OUT=7, SR=2.
// feats: [2,256,200,200],[2,256,100,100],[2,256,50,50],[2,256,25,25] fp32
// boxes: [2,256,4] fp32 -> out: [512,256,7,7] fp32
//
// v10: direct gather (v7 memory pattern) restructured for occupancy.
// grid = 1024: 2 blocks per RoI (128 channels each). Within a block,
// warp PAIR = channel stream; warp-half 0 handles bins 0..31, warp-half 1
// handles bins 32..48 (lanes >= 17 predicated off entirely). Each warp
// carries ONE register-resident geometry set (16 values) -> ~half the regs
// of v7 -> 4-5 blocks/SM. No smem in the hot loop, no barriers, no shfl.

#define NLVL 4

__global__ __launch_bounds__(256) void roi_align_kernel(
    const float* __restrict__ f0, const float* __restrict__ f1,
    const float* __restrict__ f2, const float* __restrict__ f3,
    const float* __restrict__ boxes, float* __restrict__ out)
{
    const int blk   = blockIdx.x;
    const int r     = blk >> 1;        // roi 0..511
    const int chalf = blk & 1;         // channel half: 0 -> 0..127, 1 -> 128..255
    const int tid   = threadIdx.x;
    const int w     = tid >> 5;        // warp 0..7
    const int pair  = w >> 1;          // channel stream 0..3
    const int half  = w & 1;           // 0: bins 0..31, 1: bins 32..48
    const int lane  = tid & 31;
    const int b     = r >> 8;

    // ---- per-RoI geometry ----
    const float bx1 = boxes[r * 4 + 0];
    const float by1 = boxes[r * 4 + 1];
    const float bx2 = boxes[r * 4 + 2];
    const float by2 = boxes[r * 4 + 3];

    const float area = (bx2 - bx1) * (by2 - by1);
    float lv = floorf(4.0f + log2f(sqrtf(area) / 224.0f + 1e-6f));
    lv = fminf(fmaxf(lv, 2.0f), 5.0f);
    const int level = (int)lv - 2;

    const int   Htab[NLVL]  = {200, 100, 50, 25};
    const float sctab[NLVL] = {0.25f, 0.125f, 0.0625f, 0.03125f};
    const int   H  = Htab[level];
    const int   W  = H;
    const float sc = sctab[level];
    const float* feat = (level == 0) ? f0 : (level == 1) ? f1 : (level == 2) ? f2 : f3;

    const float x1 = bx1 * sc, y1 = by1 * sc;
    const float roi_w = fmaxf(bx2 * sc - x1, 1.0f);
    const float roi_h = fmaxf(by2 * sc - y1, 1.0f);
    const float bin_w = roi_w / 7.0f;
    const float bin_h = roi_h / 7.0f;

    // ---- this lane's bin ----
    const int  bin_raw = half * 32 + lane;
    const bool live    = (bin_raw < 49);
    const int  bin     = live ? bin_raw : 0;
    const int  ph = bin / 7;
    const int  pw = bin - 7 * ph;

    // ---- per-lane bin geometry: ONE set, in registers ----
    int   Ry[4], Xc[4];
    float Cy[4], Cx[4];

    #pragma unroll
    for (int s = 0; s < 2; s++) {
        // y tap (jy = 2*ph + s)
        {
            const float g   = (float)ph + ((float)s + 0.5f) * 0.5f;
            float pos = y1 + g * bin_h;
            const float vld = (pos >= -1.0f && pos <= (float)H) ? 0.25f : 0.0f; // fold /4
            pos = fmaxf(pos, 0.0f);
            int lo = (int)pos, hi;
            if (lo >= H - 1) { lo = H - 1; hi = H - 1; pos = (float)lo; }
            else             { hi = lo + 1; }
            const float fr = pos - (float)lo;
            Ry[2 * s + 0] = lo * W;
            Ry[2 * s + 1] = hi * W;
            Cy[2 * s + 0] = vld * (1.0f - fr);
            Cy[2 * s + 1] = vld * fr;
        }
        // x tap (jx = 2*pw + s)
        {
            const float g   = (float)pw + ((float)s + 0.5f) * 0.5f;
            float pos = x1 + g * bin_w;
            const float vld = (pos >= -1.0f && pos <= (float)W) ? 1.0f : 0.0f;
            pos = fmaxf(pos, 0.0f);
            int lo = (int)pos, hi;
            if (lo >= W - 1) { lo = W - 1; hi = W - 1; pos = (float)lo; }
            else             { hi = lo + 1; }
            const float fr = pos - (float)lo;
            Xc[2 * s + 0] = lo;
            Xc[2 * s + 1] = hi;
            Cx[2 * s + 0] = vld * (1.0f - fr);
            Cx[2 * s + 1] = vld * fr;
        }
    }

    // ---- sweep 32 channels per warp pair ----
    const size_t plane = (size_t)H * W;
    const int c0 = chalf * 128 + pair * 32;
    const float* fp = feat + ((size_t)b * 256 + c0) * plane;
    float* op = out + ((size_t)r * 256 + c0) * 49 + bin;

    if (live) {
        #pragma unroll 1
        for (int k = 0; k < 32; k++) {
            float acc = 0.0f;
            #pragma unroll
            for (int i = 0; i < 4; i++) {
                const float* A = fp + Ry[i];
                acc += Cy[i] * (Cx[0] * A[Xc[0]] + Cx[1] * A[Xc[1]]
                              + Cx[2] * A[Xc[2]] + Cx[3] * A[Xc[3]]);
            }
            *op = acc;
            fp += plane;
            op += 49;
        }
    }
}

extern "C" void kernel_launch(void* const* d_in, const int* in_sizes, int n_in,
                              void* d_out, int out_size) {
    const int nroi = in_sizes[4] / 4;   // 512
    roi_align_kernel<<<nroi * 2, 256>>>(
        (const float*)d_in[0], (const float*)d_in[1],
        (const float*)d_in[2], (const float*)d_in[3],
        (const float*)d_in[4], (float*)d_out);
}

// round 11
// speedup vs baseline: 2.8819x; 1.3950x over previous
#include <cuda_runtime.h>

// MultiScaleRoIAlign: 4-level FPN, RoIAlign(aligned=False), OUT=7, SR=2.
// feats: [2,256,200,200],[2,256,100,100],[2,256,50,50],[2,256,25,25] fp32
// boxes: [2,256,4] fp32 -> out: [512,256,7,7] fp32
//
// v11: v10 structure (warp-pair = channel stream, warp-half 0 -> bins 0..31,
// warp-half 1 -> bins 32..48, ONE register geometry set per warp) with:
//  - grid 2048: 4 blocks per RoI (64 channels each) for finer wave balance
//  - x2 channel unroll inside the sweep (two independent plane streams,
//    MLP 32 per warp) -- geometry unchanged, so register cost stays small.

#define NLVL 4

__global__ __launch_bounds__(256) void roi_align_kernel(
    const float* __restrict__ f0, const float* __restrict__ f1,
    const float* __restrict__ f2, const float* __restrict__ f3,
    const float* __restrict__ boxes, float* __restrict__ out)
{
    const int blk   = blockIdx.x;
    const int r     = blk >> 2;        // roi 0..511
    const int cq    = blk & 3;         // channel quarter: 64 channels
    const int tid   = threadIdx.x;
    const int w     = tid >> 5;        // warp 0..7
    const int pair  = w >> 1;          // channel stream 0..3 (16 ch each)
    const int half  = w & 1;           // 0: bins 0..31, 1: bins 32..48
    const int lane  = tid & 31;
    const int b     = r >> 8;

    // ---- per-RoI geometry ----
    const float bx1 = boxes[r * 4 + 0];
    const float by1 = boxes[r * 4 + 1];
    const float bx2 = boxes[r * 4 + 2];
    const float by2 = boxes[r * 4 + 3];

    const float area = (bx2 - bx1) * (by2 - by1);
    float lv = floorf(4.0f + log2f(sqrtf(area) / 224.0f + 1e-6f));
    lv = fminf(fmaxf(lv, 2.0f), 5.0f);
    const int level = (int)lv - 2;

    const int   Htab[NLVL]  = {200, 100, 50, 25};
    const float sctab[NLVL] = {0.25f, 0.125f, 0.0625f, 0.03125f};
    const int   H  = Htab[level];
    const int   W  = H;
    const float sc = sctab[level];
    const float* feat = (level == 0) ? f0 : (level == 1) ? f1 : (level == 2) ? f2 : f3;

    const float x1 = bx1 * sc, y1 = by1 * sc;
    const float roi_w = fmaxf(bx2 * sc - x1, 1.0f);
    const float roi_h = fmaxf(by2 * sc - y1, 1.0f);
    const float bin_w = roi_w / 7.0f;
    const float bin_h = roi_h / 7.0f;

    // ---- this lane's bin ----
    const int  bin_raw = half * 32 + lane;
    const bool live    = (bin_raw < 49);
    const int  bin     = live ? bin_raw : 0;
    const int  ph = bin / 7;
    const int  pw = bin - 7 * ph;

    // ---- per-lane bin geometry: ONE set, in registers ----
    int   Ry[4], Xc[4];
    float Cy[4], Cx[4];

    #pragma unroll
    for (int s = 0; s < 2; s++) {
        // y tap (jy = 2*ph + s)
        {
            const float g   = (float)ph + ((float)s + 0.5f) * 0.5f;
            float pos = y1 + g * bin_h;
            const float vld = (pos >= -1.0f && pos <= (float)H) ? 0.25f : 0.0f; // fold /4
            pos = fmaxf(pos, 0.0f);
            int lo = (int)pos, hi;
            if (lo >= H - 1) { lo = H - 1; hi = H - 1; pos = (float)lo; }
            else             { hi = lo + 1; }
            const float fr = pos - (float)lo;
            Ry[2 * s + 0] = lo * W;
            Ry[2 * s + 1] = hi * W;
            Cy[2 * s + 0] = vld * (1.0f - fr);
            Cy[2 * s + 1] = vld * fr;
        }
        // x tap (jx = 2*pw + s)
        {
            const float g   = (float)pw + ((float)s + 0.5f) * 0.5f;
            float pos = x1 + g * bin_w;
            const float vld = (pos >= -1.0f && pos <= (float)W) ? 1.0f : 0.0f;
            pos = fmaxf(pos, 0.0f);
            int lo = (int)pos, hi;
            if (lo >= W - 1) { lo = W - 1; hi = W - 1; pos = (float)lo; }
            else             { hi = lo + 1; }
            const float fr = pos - (float)lo;
            Xc[2 * s + 0] = lo;
            Xc[2 * s + 1] = hi;
            Cx[2 * s + 0] = vld * (1.0f - fr);
            Cx[2 * s + 1] = vld * fr;
        }
    }

    // ---- sweep 16 channels per warp pair, x2 unrolled ----
    const size_t plane = (size_t)H * W;
    const int c0 = cq * 64 + pair * 16;
    const float* fp = feat + ((size_t)b * 256 + c0) * plane;
    float* op = out + ((size_t)r * 256 + c0) * 49 + bin;

    if (live) {
        #pragma unroll 1
        for (int k = 0; k < 16; k += 2) {
            const float* fpa = fp;
            const float* fpb = fp + plane;
            float acc_a = 0.0f, acc_b = 0.0f;
            #pragma unroll
            for (int i = 0; i < 4; i++) {
                const float* A = fpa + Ry[i];
                const float* B = fpb + Ry[i];
                acc_a += Cy[i] * (Cx[0] * A[Xc[0]] + Cx[1] * A[Xc[1]]
                                + Cx[2] * A[Xc[2]] + Cx[3] * A[Xc[3]]);
                acc_b += Cy[i] * (Cx[0] * B[Xc[0]] + Cx[1] * B[Xc[1]]
                                + Cx[2] * B[Xc[2]] + Cx[3] * B[Xc[3]]);
            }
            op[0]  = acc_a;
            op[49] = acc_b;
            fp += 2 * plane;
            op += 2 * 49;
        }
    }
}

extern "C" void kernel_launch(void* const* d_in, const int* in_sizes, int n_in,
                              void* d_out, int out_size) {
    const int nroi = in_sizes[4] / 4;   // 512
    roi_align_kernel<<<nroi * 4, 256>>>(
        (const float*)d_in[0], (const float*)d_in[1],
        (const float*)d_in[2], (const float*)d_in[3],
        (const float*)d_in[4], (float*)d_out);
}